// round 14
// baseline (speedup 1.0000x reference)
#include <cuda_runtime.h>
#include <math.h>
#include <stdint.h>

// Problem dims
#define Bb   64
#define Tt   2048
#define INx  64
#define Hh   512
#define OUTD 32
#define K1   576      // INx + Hh
#define NCTA 132      // 4 groups x 33 CTAs, 1 CTA/SM
#define GRP  4        // independent batch groups
#define CPG  33       // CTAs per group: lc 0..15 f, 16..31 z, 32 y; lc<32 also phase-2
#define BG   16       // batch rows per group
#define NC1g 32       // phase-1 cols per CTA
#define NC2g 16       // phase-2 cols per CTA (lc<32)
#define NTHR 512
#define NSL  16       // K-slices: warp ks owns 32 x-rows + 4 u-rows

typedef unsigned long long ull;

// ---- persistent device scratch (no allocation allowed) ----
__device__ float g_x  [2 * Hh * Bb];           // state double buffer, [buf][k][m]
__device__ float g_xfT[Hh * Bb];               // f*x, transposed  [k][m]
__device__ float g_z  [Hh * Bb];               // z gate           [j][m]
__device__ float g_uT [(size_t)Tt * INx * Bb]; // u transposed: [t][i][m]  (32 MB)
__device__ unsigned g_bar;                     // one-time global init barrier
// dataflow flags (value = completed step + 1), each on its own 128B line
__device__ unsigned g_flagX[GRP * 32 * 32];
__device__ unsigned g_flagF[GRP * 16 * 32];
__device__ unsigned g_flagZ[GRP * 16 * 32];
__device__ unsigned g_flagY[GRP * 32];
#define FLX(g,i) (g_flagX + ((g) * 32 + (i)) * 32)
#define FLF(g,i) (g_flagF + ((g) * 16 + (i)) * 32)
#define FLZ(g,i) (g_flagZ + ((g) * 16 + (i)) * 32)
#define FLY(g)   (g_flagY + (g) * 32)

// SMEM layout (floats) in dynamic shared memory
#define OFF_W1  0                    // 576*32 = 18432
#define OFF_W2  18432                // 576*16 =  9216
#define OFF_RED 27648                // 16*32*16 = 8192 (also transpose tile: 4160)
#define OFF_B1  35840                // 32
#define OFF_B2  35872                // 16
#define SMEM_FLOATS 35888
#define SMEM_BYTES  (SMEM_FLOATS * 4)

__device__ __forceinline__ ull bcast2(float v) {
  ull r;
  asm("mov.b64 %0, {%1, %1};" : "=l"(r) : "r"(__float_as_uint(v)));
  return r;
}
__device__ __forceinline__ unsigned poll_at(const unsigned* p) {
  unsigned v;
  asm volatile("ld.acquire.gpu.global.u32 %0, [%1];" : "=r"(v) : "l"(p) : "memory");
  return v;
}
__device__ __forceinline__ void wait_flag(const unsigned* p, unsigned need) {
  while (poll_at(p) < need) { }
}
__device__ __forceinline__ void set_flag(unsigned* p, unsigned v) {
  asm volatile("st.release.gpu.global.u32 [%0], %1;" :: "l"(p), "r"(v) : "memory");
}
__device__ __forceinline__ void unpack2(ull a, float& lo, float& hi) {
  unsigned l, h;
  asm("mov.b64 {%0,%1}, %2;" : "=r"(l), "=r"(h) : "l"(a));
  lo = __uint_as_float(l); hi = __uint_as_float(h);
}

__global__ void __launch_bounds__(NTHR, 1) gru_main(
    const float* __restrict__ u,
    const float* __restrict__ x0,
    const float* __restrict__ kernel_fz, const float* __restrict__ bias_fz,
    const float* __restrict__ kernel_r,  const float* __restrict__ bias_r,
    const float* __restrict__ W_out,     const float* __restrict__ b_out,
    float* __restrict__ out)
{
  extern __shared__ float smem[];
  float* s_w1  = smem + OFF_W1;   // [kk][32], kk 0..511 = x rows, 512..575 = u rows
  float* s_w2  = smem + OFF_W2;   // [kk][16]
  float* s_red = smem + OFF_RED;  // [ks][n][BG] — conflict-free
  float* s_b1  = smem + OFF_B1;
  float* s_b2  = smem + OFF_B2;

  const int tid = threadIdx.x;
  const int cid = blockIdx.x;
  const int grp = cid / CPG;          // batch group 0..3
  const int lc  = cid - grp * CPG;    // 0..32 within group
  const int gbase = grp * BG;         // first batch row of group
  const int mg  = tid & 7;            // m-pair within group (rows 2mg, 2mg+1)
  const int cs  = (tid >> 3) & 3;     // column split
  const int ks  = tid >> 5;           // K-slice 0..15
  const int m0  = 2 * mg;

  // ---- stationary weight slices into SMEM ----
  for (int i = tid; i < K1 * NC1g; i += NTHR) {
    int kk = i / NC1g, n = i % NC1g;
    int c  = lc * NC1g + n;
    int row = (kk < Hh) ? (INx + kk) : (kk - Hh);   // concat order: [u | x]
    float w;
    if (c < 2 * Hh) w = kernel_fz[row * (2 * Hh) + c];
    else { int o = c - 2 * Hh; w = (kk < Hh) ? W_out[o * Hh + kk] : 0.0f; }
    s_w1[i] = w;
  }
  if (lc < 32) {
    for (int i = tid; i < K1 * NC2g; i += NTHR) {
      int kk = i / NC2g, n = i % NC2g;
      int j  = lc * NC2g + n;
      int row = (kk < Hh) ? (INx + kk) : (kk - Hh);
      s_w2[i] = kernel_r[row * Hh + j];
    }
  }
  if (tid < NC1g) {
    int c = lc * NC1g + tid;
    s_b1[tid] = (c < 2 * Hh) ? bias_fz[c] : b_out[c - 2 * Hh];
  }
  if (lc < 32 && tid < NC2g) s_b2[tid] = bias_r[lc * NC2g + tid];

  // ---- in-kernel init: x0 -> g_x[buf 0] (grid-stride) ----
  for (int idx = cid * NTHR + tid; idx < Hh * Bb; idx += NCTA * NTHR) {
    int k = idx >> 6, mm = idx & 63;
    g_x[idx] = x0[mm * Hh + k];           // x0 is (64, 1, 512)
  }

  // ---- in-kernel u transpose: u(B,T,IN) -> g_uT[t][i][m] ----
  {
    float* tile = s_red;                  // 64*65 = 4160 floats fits in RED region
    __syncthreads();
    for (int t = cid; t < Tt; t += NCTA) {
      for (int idx = tid; idx < INx * Bb; idx += NTHR) {
        int mm = idx >> 6, i = idx & 63;
        tile[mm * 65 + i] = u[((size_t)mm * Tt + t) * INx + i];
      }
      __syncthreads();
      for (int idx = tid; idx < INx * Bb; idx += NTHR) {
        g_uT[(size_t)t * (INx * Bb) + idx] = tile[(idx & 63) * 65 + (idx >> 6)];
      }
      __syncthreads();
    }
  }

  // ---- one-time GLOBAL barrier after init/transpose ----
  __threadfence();
  __syncthreads();
  if (tid == 0) atomicAdd(&g_bar, 1u);
  if (tid == 0) { while (poll_at(&g_bar) < NCTA) { } }
  __syncthreads();

  for (int t = 0; t < Tt; t++) {
    const float* uT_t  = g_uT + (size_t)t * (INx * Bb);
    const float* xbuf  = g_x + (t & 1) * (Hh * Bb);
    float*       xnext = g_x + ((t + 1) & 1) * (Hh * Bb);

    // ================= phase 1: fz logits + y readout =================
    {
      ull acc[8];
      #pragma unroll
      for (int p = 0; p < 8; p++) acc[p] = 0ull;

      { // u segment (no dependencies): rows [512+ks*4, +4)
        const float2* up = (const float2*)(uT_t + (ks * 4) * Bb + gbase + m0);
        const float*  wp = s_w1 + (Hh + ks * 4) * NC1g + cs * 8;
        #pragma unroll
        for (int k = 0; k < 4; k++) {
          float2 xv = up[k * (Bb / 2)];
          ull x0b = bcast2(xv.x), x1b = bcast2(xv.y);
          const ulonglong2* wv = (const ulonglong2*)(wp + k * NC1g);
          ulonglong2 wA = wv[0], wB = wv[1];
          asm("fma.rn.f32x2 %0, %1, %2, %0;" : "+l"(acc[0]) : "l"(x0b), "l"(wA.x));
          asm("fma.rn.f32x2 %0, %1, %2, %0;" : "+l"(acc[1]) : "l"(x0b), "l"(wA.y));
          asm("fma.rn.f32x2 %0, %1, %2, %0;" : "+l"(acc[2]) : "l"(x0b), "l"(wB.x));
          asm("fma.rn.f32x2 %0, %1, %2, %0;" : "+l"(acc[3]) : "l"(x0b), "l"(wB.y));
          asm("fma.rn.f32x2 %0, %1, %2, %0;" : "+l"(acc[4]) : "l"(x1b), "l"(wA.x));
          asm("fma.rn.f32x2 %0, %1, %2, %0;" : "+l"(acc[5]) : "l"(x1b), "l"(wA.y));
          asm("fma.rn.f32x2 %0, %1, %2, %0;" : "+l"(acc[6]) : "l"(x1b), "l"(wB.x));
          asm("fma.rn.f32x2 %0, %1, %2, %0;" : "+l"(acc[7]) : "l"(x1b), "l"(wB.y));
        }
      }

      // wait for x(t) slices owned by this warp (producers: phase-2 CTAs 2ks, 2ks+1)
      wait_flag(FLX(grp, 2 * ks),     (unsigned)t);
      wait_flag(FLX(grp, 2 * ks + 1), (unsigned)t);

      { // x segment: rows [ks*32, ks*32+32), register staging
        const float2* xp = (const float2*)(xbuf + (ks * 32) * Bb + gbase + m0);
        const float*  wp = s_w1 + (ks * 32) * NC1g + cs * 8;
        float2 buf[8];
        #pragma unroll
        for (int j = 0; j < 8; j++) buf[j] = __ldcg(xp + j * (Bb / 2));
        #pragma unroll
        for (int blk = 0; blk < 4; blk++) {
          float2 nbuf[8];
          if (blk < 3) {
            #pragma unroll
            for (int j = 0; j < 8; j++)
              nbuf[j] = __ldcg(xp + ((blk + 1) * 8 + j) * (Bb / 2));
          }
          #pragma unroll
          for (int j = 0; j < 8; j++) {
            int k = blk * 8 + j;
            ull x0b = bcast2(buf[j].x), x1b = bcast2(buf[j].y);
            const ulonglong2* wv = (const ulonglong2*)(wp + k * NC1g);
            ulonglong2 wA = wv[0], wB = wv[1];
            asm("fma.rn.f32x2 %0, %1, %2, %0;" : "+l"(acc[0]) : "l"(x0b), "l"(wA.x));
            asm("fma.rn.f32x2 %0, %1, %2, %0;" : "+l"(acc[1]) : "l"(x0b), "l"(wA.y));
            asm("fma.rn.f32x2 %0, %1, %2, %0;" : "+l"(acc[2]) : "l"(x0b), "l"(wB.x));
            asm("fma.rn.f32x2 %0, %1, %2, %0;" : "+l"(acc[3]) : "l"(x0b), "l"(wB.y));
            asm("fma.rn.f32x2 %0, %1, %2, %0;" : "+l"(acc[4]) : "l"(x1b), "l"(wA.x));
            asm("fma.rn.f32x2 %0, %1, %2, %0;" : "+l"(acc[5]) : "l"(x1b), "l"(wA.y));
            asm("fma.rn.f32x2 %0, %1, %2, %0;" : "+l"(acc[6]) : "l"(x1b), "l"(wB.x));
            asm("fma.rn.f32x2 %0, %1, %2, %0;" : "+l"(acc[7]) : "l"(x1b), "l"(wB.y));
          }
          #pragma unroll
          for (int j = 0; j < 8; j++) buf[j] = nbuf[j];
        }
      }
      { // store partials, layout [ks][n][BG]: float2(m0,m1) per column — conflict-free
        float* rp = s_red + ks * (NC1g * BG);
        int colb = cs * 8;
        #pragma unroll
        for (int p = 0; p < 4; p++) {
          float e0, o0, e1, o1;
          unpack2(acc[p],     e0, o0);
          unpack2(acc[4 + p], e1, o1);
          float2 ve; ve.x = e0; ve.y = e1;
          float2 vo; vo.x = o0; vo.y = o1;
          *(float2*)(rp + (colb + 2 * p)     * BG + m0) = ve;
          *(float2*)(rp + (colb + 2 * p + 1) * BG + m0) = vo;
        }
      }
      __syncthreads();

      { // epilogue: 512 threads -> 16 batch x 32 cols
        int mm = tid & 15, n = tid >> 4;       // n 0..31
        float s = s_b1[n];
        #pragma unroll
        for (int q = 0; q < NSL; q++) s += s_red[q * (NC1g * BG) + n * BG + mm];
        int c   = lc * NC1g + n;
        int mgl = gbase + mm;
        if (c < Hh) {                                  // f gate -> f*x
          float f  = 1.0f / (1.0f + expf(-s));
          g_xfT[c * Bb + mgl] = f * __ldcg(&xbuf[c * Bb + mgl]);
        } else if (c < 2 * Hh) {                       // z gate
          g_z[(c - Hh) * Bb + mgl] = 1.0f / (1.0f + expf(-s));
        } else {                                       // y readout (pre-update x)
          out[((size_t)mgl * Tt + t) * OUTD + (c - 2 * Hh)] = s;
        }
      }
      __threadfence();
      __syncthreads();
      if (tid == 0) {
        if (lc < 16)      set_flag(FLF(grp, lc),      (unsigned)(t + 1));
        else if (lc < 32) set_flag(FLZ(grp, lc - 16), (unsigned)(t + 1));
        else              set_flag(FLY(grp),          (unsigned)(t + 1));
      }
    }

    // ================= phase 2: r + state update =================
    if (lc < 32) {
      ull acc2[4] = {0ull, 0ull, 0ull, 0ull};

      { // u segment (no dependencies)
        const float2* up = (const float2*)(uT_t + (ks * 4) * Bb + gbase + m0);
        const float*  wp = s_w2 + (Hh + ks * 4) * NC2g + cs * 4;
        #pragma unroll
        for (int k = 0; k < 4; k++) {
          float2 xv = up[k * (Bb / 2)];
          ull x0b = bcast2(xv.x), x1b = bcast2(xv.y);
          ulonglong2 wA = *(const ulonglong2*)(wp + k * NC2g);
          asm("fma.rn.f32x2 %0, %1, %2, %0;" : "+l"(acc2[0]) : "l"(x0b), "l"(wA.x));
          asm("fma.rn.f32x2 %0, %1, %2, %0;" : "+l"(acc2[1]) : "l"(x0b), "l"(wA.y));
          asm("fma.rn.f32x2 %0, %1, %2, %0;" : "+l"(acc2[2]) : "l"(x1b), "l"(wA.x));
          asm("fma.rn.f32x2 %0, %1, %2, %0;" : "+l"(acc2[3]) : "l"(x1b), "l"(wA.y));
        }
      }

      // wait for f*x(t) rows owned by this warp (producer: phase-1 CTA ks)
      wait_flag(FLF(grp, ks), (unsigned)(t + 1));

      { // x segment with register staging: g_xfT rows [ks*32, +32)
        const float2* xp = (const float2*)(g_xfT + (ks * 32) * Bb + gbase + m0);
        const float*  wp = s_w2 + (ks * 32) * NC2g + cs * 4;
        float2 buf[8];
        #pragma unroll
        for (int j = 0; j < 8; j++) buf[j] = __ldcg(xp + j * (Bb / 2));
        #pragma unroll
        for (int blk = 0; blk < 4; blk++) {
          float2 nbuf[8];
          if (blk < 3) {
            #pragma unroll
            for (int j = 0; j < 8; j++)
              nbuf[j] = __ldcg(xp + ((blk + 1) * 8 + j) * (Bb / 2));
          }
          #pragma unroll
          for (int j = 0; j < 8; j++) {
            int k = blk * 8 + j;
            ull x0b = bcast2(buf[j].x), x1b = bcast2(buf[j].y);
            ulonglong2 wA = *(const ulonglong2*)(wp + k * NC2g);
            asm("fma.rn.f32x2 %0, %1, %2, %0;" : "+l"(acc2[0]) : "l"(x0b), "l"(wA.x));
            asm("fma.rn.f32x2 %0, %1, %2, %0;" : "+l"(acc2[1]) : "l"(x0b), "l"(wA.y));
            asm("fma.rn.f32x2 %0, %1, %2, %0;" : "+l"(acc2[2]) : "l"(x1b), "l"(wA.x));
            asm("fma.rn.f32x2 %0, %1, %2, %0;" : "+l"(acc2[3]) : "l"(x1b), "l"(wA.y));
          }
          #pragma unroll
          for (int j = 0; j < 8; j++) buf[j] = nbuf[j];
        }
      }
      { // store partials, layout [ks][n][BG], conflict-free
        float* rp = s_red + ks * (NC2g * BG);
        int colb = cs * 4;
        #pragma unroll
        for (int p = 0; p < 2; p++) {
          float e0, o0, e1, o1;
          unpack2(acc2[p],     e0, o0);
          unpack2(acc2[2 + p], e1, o1);
          float2 ve; ve.x = e0; ve.y = e1;
          float2 vo; vo.x = o0; vo.y = o1;
          *(float2*)(rp + (colb + 2 * p)     * BG + m0) = ve;
          *(float2*)(rp + (colb + 2 * p + 1) * BG + m0) = vo;
        }
      }
      __syncthreads();

      if (tid < 256) {                  // 16 batch x 16 cols
        // z producer for rows [lc*16, lc*16+16) is z-CTA (lc>>1); y-CTA guards x reuse
        wait_flag(FLZ(grp, lc >> 1), (unsigned)(t + 1));
        wait_flag(FLY(grp),          (unsigned)t);
        int mm = tid & 15, n = tid >> 4;     // n 0..15
        float s = s_b2[n];
        #pragma unroll
        for (int q = 0; q < NSL; q++) s += s_red[q * (NC2g * BG) + n * BG + mm];
        int j   = lc * NC2g + n;
        int mgl = gbase + mm;
        float r  = tanhf(s);
        float z  = __ldcg(&g_z[j * Bb + mgl]);
        float xo = __ldcg(&xbuf[j * Bb + mgl]);
        xnext[j * Bb + mgl] = (1.0f - z) * xo + z * r;
      }
      __threadfence();
      __syncthreads();
      if (tid == 0) set_flag(FLX(grp, lc), (unsigned)(t + 1));
    }
  }
}

// Runs BEFORE gru_main each invocation: resets barrier + all dataflow flags
// and keeps gru_main as ncu launch #6 (-s 5 -c 1).
__global__ void zero_bar_kernel() {
  g_bar = 0u;
  for (int i = 0; i < GRP * 32; i++) g_flagX[i * 32] = 0u;
  for (int i = 0; i < GRP * 16; i++) { g_flagF[i * 32] = 0u; g_flagZ[i * 32] = 0u; }
  for (int g = 0; g < GRP; g++) g_flagY[g * 32] = 0u;
}

extern "C" void kernel_launch(void* const* d_in, const int* in_sizes, int n_in,
                              void* d_out, int out_size) {
  // Resolve inputs by UNIQUE element counts (immune to metadata ordering).
  const float *u = 0, *x0 = 0, *kernel_fz = 0, *bias_fz = 0,
              *kernel_r = 0, *bias_r = 0, *W_out = 0, *b_out = 0;
  for (int i = 0; i < n_in; i++) {
    const float* p = (const float*)d_in[i];
    switch (in_sizes[i]) {
      case 8388608: u         = p; break;  // 64*2048*64
      case 32768:   x0        = p; break;  // 64*1*512
      case 589824:  kernel_fz = p; break;  // 576*1024
      case 1024:    bias_fz   = p; break;
      case 294912:  kernel_r  = p; break;  // 576*512
      case 512:     bias_r    = p; break;
      case 16384:   W_out     = p; break;  // 32*512
      case 32:      b_out     = p; break;
      default: break;
    }
  }
  if (!u || !x0 || !kernel_fz || !bias_fz || !kernel_r || !bias_r || !W_out || !b_out) {
    u         = (const float*)d_in[0];
    x0        = (const float*)d_in[1];
    kernel_fz = (const float*)d_in[2];
    bias_fz   = (const float*)d_in[3];
    kernel_r  = (const float*)d_in[4];
    bias_r    = (const float*)d_in[5];
    W_out     = (const float*)d_in[6];
    b_out     = (const float*)d_in[7];
  }
  float* out = (float*)d_out;

  static int smem_set = 0;
  if (!smem_set) {
    cudaFuncSetAttribute(gru_main, cudaFuncAttributeMaxDynamicSharedMemorySize,
                         SMEM_BYTES);
    smem_set = 1;
  }

  zero_bar_kernel<<<1, 1>>>();

  void* args[] = { (void*)&u, (void*)&x0,
                   (void*)&kernel_fz, (void*)&bias_fz, (void*)&kernel_r,
                   (void*)&bias_r,    (void*)&W_out,   (void*)&b_out,
                   (void*)&out };
  cudaLaunchCooperativeKernel((const void*)gru_main, dim3(NCTA), dim3(NTHR),
                              args, SMEM_BYTES, (cudaStream_t)0);
}

// round 15
// speedup vs baseline: 1.2284x; 1.2284x over previous
#include <cuda_runtime.h>
#include <math.h>
#include <stdint.h>

// Problem dims
#define Bb   64
#define Tt   2048
#define INx  64
#define Hh   512
#define OUTD 32
#define K1   576      // INx + Hh
#define NCTA 132      // 4 groups x 33 CTAs
#define GRP  4        // independent batch groups
#define CPG  33       // CTAs per group (32 p1-cols each; lc=32 = the 32 y cols)
#define BG   16       // batch rows per group
#define NC1g 32       // phase-1 cols per CTA
#define NC2g 16       // phase-2 cols per CTA (lc<32)
#define NTHR 512
#define NSL  16       // K-slices: 16 x (32 x-rows + 4 u-rows)

typedef unsigned long long ull;

// ---- persistent device scratch (no allocation allowed) ----
__device__ float g_xT [Hh * Bb];               // state, transposed [k][m]
__device__ float g_xfT[Hh * Bb];               // f*x, transposed  [k][m]
__device__ float g_z  [Hh * Bb];               // z gate           [j][m]
__device__ float g_uT [(size_t)Tt * INx * Bb]; // u transposed: [t][i][m]  (32 MB)
__device__ unsigned g_bar;                     // one-time global init barrier
__device__ unsigned g_barG[GRP * 32];          // per-group counters, 128B apart

// SMEM layout (floats) in dynamic shared memory
#define OFF_W1  0                    // 576*32 = 18432
#define OFF_W2  18432                // 576*16 =  9216
#define OFF_RED 27648                // 16*32*16 = 8192 (also transpose tile: 4160)
#define OFF_B1  35840                // 32
#define OFF_B2  35872                // 16
#define SMEM_FLOATS 35888
#define SMEM_BYTES  (SMEM_FLOATS * 4)

__device__ __forceinline__ ull bcast2(float v) {
  ull r;
  asm("mov.b64 %0, {%1, %1};" : "=l"(r) : "r"(__float_as_uint(v)));
  return r;
}
__device__ __forceinline__ unsigned poll_at(const unsigned* p) {
  unsigned v;
  asm volatile("ld.acquire.gpu.global.u32 %0, [%1];" : "=r"(v) : "l"(p) : "memory");
  return v;
}
// Release-arrive: orders this CTA's prior writes (all threads, via the
// preceding bar.sync happens-before) ahead of the counter increment.
// Replaces per-thread MEMBAR.GPU — the standard cooperative-groups pattern.
__device__ __forceinline__ void arrive_release(unsigned* p) {
  asm volatile("red.release.gpu.global.add.u32 [%0], %1;" :: "l"(p), "r"(1u) : "memory");
}
__device__ __forceinline__ void unpack2(ull a, float& lo, float& hi) {
  unsigned l, h;
  asm("mov.b64 {%0,%1}, %2;" : "=r"(l), "=r"(h) : "l"(a));
  lo = __uint_as_float(l); hi = __uint_as_float(h);
}

__global__ void __launch_bounds__(NTHR, 1) gru_main(
    const float* __restrict__ u,
    const float* __restrict__ x0,
    const float* __restrict__ kernel_fz, const float* __restrict__ bias_fz,
    const float* __restrict__ kernel_r,  const float* __restrict__ bias_r,
    const float* __restrict__ W_out,     const float* __restrict__ b_out,
    float* __restrict__ out)
{
  extern __shared__ float smem[];
  float* s_w1  = smem + OFF_W1;   // [kk][32], kk 0..511 = x rows, 512..575 = u rows
  float* s_w2  = smem + OFF_W2;   // [kk][16]
  float* s_red = smem + OFF_RED;  // [ks][n][BG] — conflict-free
  float* s_b1  = smem + OFF_B1;
  float* s_b2  = smem + OFF_B2;

  const int tid = threadIdx.x;
  const int cid = blockIdx.x;
  const int grp = cid / CPG;          // batch group 0..3
  const int lc  = cid - grp * CPG;    // 0..32 within group
  const int gbase = grp * BG;         // first batch row of group
  const int mg  = tid & 7;            // m-pair within group (rows 2mg, 2mg+1)
  const int cs  = (tid >> 3) & 3;     // column split
  const int ks  = tid >> 5;           // K-slice 0..15
  const int m0  = 2 * mg;
  unsigned* barp = &g_barG[grp * 32];

  // ---- stationary weight slices into SMEM ----
  for (int i = tid; i < K1 * NC1g; i += NTHR) {
    int kk = i / NC1g, n = i % NC1g;
    int c  = lc * NC1g + n;
    int row = (kk < Hh) ? (INx + kk) : (kk - Hh);   // concat order: [u | x]
    float w;
    if (c < 2 * Hh) w = kernel_fz[row * (2 * Hh) + c];
    else { int o = c - 2 * Hh; w = (kk < Hh) ? W_out[o * Hh + kk] : 0.0f; }
    s_w1[i] = w;
  }
  if (lc < 32) {
    for (int i = tid; i < K1 * NC2g; i += NTHR) {
      int kk = i / NC2g, n = i % NC2g;
      int j  = lc * NC2g + n;
      int row = (kk < Hh) ? (INx + kk) : (kk - Hh);
      s_w2[i] = kernel_r[row * Hh + j];
    }
  }
  if (tid < NC1g) {
    int c = lc * NC1g + tid;
    s_b1[tid] = (c < 2 * Hh) ? bias_fz[c] : b_out[c - 2 * Hh];
  }
  if (lc < 32 && tid < NC2g) s_b2[tid] = bias_r[lc * NC2g + tid];

  // ---- in-kernel init: x0 -> g_xT (grid-stride) ----
  for (int idx = cid * NTHR + tid; idx < Hh * Bb; idx += NCTA * NTHR) {
    int k = idx >> 6, mm = idx & 63;
    g_xT[idx] = x0[mm * Hh + k];          // x0 is (64, 1, 512)
  }

  // ---- in-kernel u transpose: u(B,T,IN) -> g_uT[t][i][m] ----
  {
    float* tile = s_red;                  // 64*65 = 4160 floats fits in RED region
    __syncthreads();
    for (int t = cid; t < Tt; t += NCTA) {
      for (int idx = tid; idx < INx * Bb; idx += NTHR) {
        int mm = idx >> 6, i = idx & 63;
        tile[mm * 65 + i] = u[((size_t)mm * Tt + t) * INx + i];
      }
      __syncthreads();
      for (int idx = tid; idx < INx * Bb; idx += NTHR) {
        g_uT[(size_t)t * (INx * Bb) + idx] = tile[(idx & 63) * 65 + (idx >> 6)];
      }
      __syncthreads();
    }
  }

  // ---- one-time GLOBAL barrier after init/transpose (cold path, keep fence) ----
  __threadfence();
  __syncthreads();
  if (tid == 0) atomicAdd(&g_bar, 1u);
  if (tid == 0) { while (poll_at(&g_bar) < NCTA) { } }
  __syncthreads();

  // ---- prologue: phase-1 u-segment for t = 0 ----
  ull acc1u[8];    // [0..3] = m0 col-pairs(01,23,45,67 of cs*8), [4..7] = m1
  {
    #pragma unroll
    for (int p = 0; p < 8; p++) acc1u[p] = 0ull;
    const float2* up = (const float2*)(g_uT + (ks * 4) * Bb + gbase + m0);
    const float*  wp = s_w1 + (Hh + ks * 4) * NC1g + cs * 8;
    #pragma unroll
    for (int k = 0; k < 4; k++) {
      float2 xv = up[k * (Bb / 2)];
      ull x0b = bcast2(xv.x), x1b = bcast2(xv.y);
      const ulonglong2* wv = (const ulonglong2*)(wp + k * NC1g);
      ulonglong2 wA = wv[0], wB = wv[1];
      asm("fma.rn.f32x2 %0, %1, %2, %0;" : "+l"(acc1u[0]) : "l"(x0b), "l"(wA.x));
      asm("fma.rn.f32x2 %0, %1, %2, %0;" : "+l"(acc1u[1]) : "l"(x0b), "l"(wA.y));
      asm("fma.rn.f32x2 %0, %1, %2, %0;" : "+l"(acc1u[2]) : "l"(x0b), "l"(wB.x));
      asm("fma.rn.f32x2 %0, %1, %2, %0;" : "+l"(acc1u[3]) : "l"(x0b), "l"(wB.y));
      asm("fma.rn.f32x2 %0, %1, %2, %0;" : "+l"(acc1u[4]) : "l"(x1b), "l"(wA.x));
      asm("fma.rn.f32x2 %0, %1, %2, %0;" : "+l"(acc1u[5]) : "l"(x1b), "l"(wA.y));
      asm("fma.rn.f32x2 %0, %1, %2, %0;" : "+l"(acc1u[6]) : "l"(x1b), "l"(wB.x));
      asm("fma.rn.f32x2 %0, %1, %2, %0;" : "+l"(acc1u[7]) : "l"(x1b), "l"(wB.y));
    }
  }

  unsigned tg = 0;
  for (int t = 0; t < Tt; t++) {
    const float* uT_t = g_uT + (size_t)t * (INx * Bb);

    // ================= phase 1: fz logits + y readout =================
    {
      ull acc[8];
      #pragma unroll
      for (int p = 0; p < 8; p++) acc[p] = acc1u[p];

      { // x segment: rows [ks*32, ks*32+32), register staging
        const float2* xp = (const float2*)(g_xT + (ks * 32) * Bb + gbase + m0);
        const float*  wp = s_w1 + (ks * 32) * NC1g + cs * 8;
        float2 buf[8];
        #pragma unroll
        for (int j = 0; j < 8; j++) buf[j] = __ldcg(xp + j * (Bb / 2));
        #pragma unroll
        for (int blk = 0; blk < 4; blk++) {
          float2 nbuf[8];
          if (blk < 3) {
            #pragma unroll
            for (int j = 0; j < 8; j++)
              nbuf[j] = __ldcg(xp + ((blk + 1) * 8 + j) * (Bb / 2));
          }
          #pragma unroll
          for (int j = 0; j < 8; j++) {
            int k = blk * 8 + j;
            ull x0b = bcast2(buf[j].x), x1b = bcast2(buf[j].y);
            const ulonglong2* wv = (const ulonglong2*)(wp + k * NC1g);
            ulonglong2 wA = wv[0], wB = wv[1];
            asm("fma.rn.f32x2 %0, %1, %2, %0;" : "+l"(acc[0]) : "l"(x0b), "l"(wA.x));
            asm("fma.rn.f32x2 %0, %1, %2, %0;" : "+l"(acc[1]) : "l"(x0b), "l"(wA.y));
            asm("fma.rn.f32x2 %0, %1, %2, %0;" : "+l"(acc[2]) : "l"(x0b), "l"(wB.x));
            asm("fma.rn.f32x2 %0, %1, %2, %0;" : "+l"(acc[3]) : "l"(x0b), "l"(wB.y));
            asm("fma.rn.f32x2 %0, %1, %2, %0;" : "+l"(acc[4]) : "l"(x1b), "l"(wA.x));
            asm("fma.rn.f32x2 %0, %1, %2, %0;" : "+l"(acc[5]) : "l"(x1b), "l"(wA.y));
            asm("fma.rn.f32x2 %0, %1, %2, %0;" : "+l"(acc[6]) : "l"(x1b), "l"(wB.x));
            asm("fma.rn.f32x2 %0, %1, %2, %0;" : "+l"(acc[7]) : "l"(x1b), "l"(wB.y));
          }
          #pragma unroll
          for (int j = 0; j < 8; j++) buf[j] = nbuf[j];
        }
      }
      { // store partials, layout [ks][n][BG]: float2(m0,m1) per column — conflict-free
        float* rp = s_red + ks * (NC1g * BG);
        int colb = cs * 8;
        #pragma unroll
        for (int p = 0; p < 4; p++) {
          float e0, o0, e1, o1;
          unpack2(acc[p],     e0, o0);
          unpack2(acc[4 + p], e1, o1);
          float2 ve; ve.x = e0; ve.y = e1;
          float2 vo; vo.x = o0; vo.y = o1;
          *(float2*)(rp + (colb + 2 * p)     * BG + m0) = ve;
          *(float2*)(rp + (colb + 2 * p + 1) * BG + m0) = vo;
        }
      }
      __syncthreads();

      { // epilogue: 512 threads -> 16 batch x 32 cols
        int mm = tid & 15, n = tid >> 4;       // n 0..31
        float s = s_b1[n];
        #pragma unroll
        for (int q = 0; q < NSL; q++) s += s_red[q * (NC1g * BG) + n * BG + mm];
        int c   = lc * NC1g + n;
        int mgl = gbase + mm;
        if (c < Hh) {                                  // f gate -> f*x
          float f  = 1.0f / (1.0f + expf(-s));
          g_xfT[c * Bb + mgl] = f * __ldcg(&g_xT[c * Bb + mgl]);
        } else if (c < 2 * Hh) {                       // z gate
          g_z[(c - Hh) * Bb + mgl] = 1.0f / (1.0f + expf(-s));
        } else {                                       // y readout (pre-update x)
          out[((size_t)mgl * Tt + t) * OUTD + (c - 2 * Hh)] = s;
        }
      }
    }
    // ---- group barrier 1: bar.sync then release-arrive (no per-thread fence) ----
    __syncthreads();
    if (tid == 0) arrive_release(barp);
    tg += CPG;

    // overlap: phase-2 u-segment (depends only on g_uT)
    ull acc2[4] = {0ull, 0ull, 0ull, 0ull}; // [0..1] m0 pairs(01,23 of cs*4), [2..3] m1
    if (lc < 32) {
      const float2* up = (const float2*)(uT_t + (ks * 4) * Bb + gbase + m0);
      const float*  wp = s_w2 + (Hh + ks * 4) * NC2g + cs * 4;
      #pragma unroll
      for (int k = 0; k < 4; k++) {
        float2 xv = up[k * (Bb / 2)];
        ull x0b = bcast2(xv.x), x1b = bcast2(xv.y);
        ulonglong2 wA = *(const ulonglong2*)(wp + k * NC2g);
        asm("fma.rn.f32x2 %0, %1, %2, %0;" : "+l"(acc2[0]) : "l"(x0b), "l"(wA.x));
        asm("fma.rn.f32x2 %0, %1, %2, %0;" : "+l"(acc2[1]) : "l"(x0b), "l"(wA.y));
        asm("fma.rn.f32x2 %0, %1, %2, %0;" : "+l"(acc2[2]) : "l"(x1b), "l"(wA.x));
        asm("fma.rn.f32x2 %0, %1, %2, %0;" : "+l"(acc2[3]) : "l"(x1b), "l"(wA.y));
      }
    }
    if (tid == 0) { while (poll_at(barp) < tg) { } }
    __syncthreads();

    // ================= phase 2: r + state update =================
    if (lc < 32) {
      { // x segment with register staging
        const float2* xp = (const float2*)(g_xfT + (ks * 32) * Bb + gbase + m0);
        const float*  wp = s_w2 + (ks * 32) * NC2g + cs * 4;
        float2 buf[8];
        #pragma unroll
        for (int j = 0; j < 8; j++) buf[j] = __ldcg(xp + j * (Bb / 2));
        #pragma unroll
        for (int blk = 0; blk < 4; blk++) {
          float2 nbuf[8];
          if (blk < 3) {
            #pragma unroll
            for (int j = 0; j < 8; j++)
              nbuf[j] = __ldcg(xp + ((blk + 1) * 8 + j) * (Bb / 2));
          }
          #pragma unroll
          for (int j = 0; j < 8; j++) {
            int k = blk * 8 + j;
            ull x0b = bcast2(buf[j].x), x1b = bcast2(buf[j].y);
            ulonglong2 wA = *(const ulonglong2*)(wp + k * NC2g);
            asm("fma.rn.f32x2 %0, %1, %2, %0;" : "+l"(acc2[0]) : "l"(x0b), "l"(wA.x));
            asm("fma.rn.f32x2 %0, %1, %2, %0;" : "+l"(acc2[1]) : "l"(x0b), "l"(wA.y));
            asm("fma.rn.f32x2 %0, %1, %2, %0;" : "+l"(acc2[2]) : "l"(x1b), "l"(wA.x));
            asm("fma.rn.f32x2 %0, %1, %2, %0;" : "+l"(acc2[3]) : "l"(x1b), "l"(wA.y));
          }
          #pragma unroll
          for (int j = 0; j < 8; j++) buf[j] = nbuf[j];
        }
      }
      { // store partials, layout [ks][n][BG], conflict-free
        float* rp = s_red + ks * (NC2g * BG);
        int colb = cs * 4;
        #pragma unroll
        for (int p = 0; p < 2; p++) {
          float e0, o0, e1, o1;
          unpack2(acc2[p],     e0, o0);
          unpack2(acc2[2 + p], e1, o1);
          float2 ve; ve.x = e0; ve.y = e1;
          float2 vo; vo.x = o0; vo.y = o1;
          *(float2*)(rp + (colb + 2 * p)     * BG + m0) = ve;
          *(float2*)(rp + (colb + 2 * p + 1) * BG + m0) = vo;
        }
      }
      __syncthreads();

      if (tid < 256) {                  // 16 batch x 16 cols
        int mm = tid & 15, n = tid >> 4;     // n 0..15
        float s = s_b2[n];
        #pragma unroll
        for (int q = 0; q < NSL; q++) s += s_red[q * (NC2g * BG) + n * BG + mm];
        int j   = lc * NC2g + n;
        int mgl = gbase + mm;
        float r  = tanhf(s);
        float z  = __ldcg(&g_z[j * Bb + mgl]);
        float xo = __ldcg(&g_xT[j * Bb + mgl]);
        g_xT[j * Bb + mgl] = (1.0f - z) * xo + z * r;
      }
    }
    // ---- group barrier 2: bar.sync then release-arrive (no per-thread fence) ----
    __syncthreads();
    if (tid == 0) arrive_release(barp);
    tg += CPG;

    // overlap: phase-1 u-segment for t+1 (clamped; last iter redundant)
    {
      int tn = (t + 1 < Tt) ? (t + 1) : (Tt - 1);
      const float2* up = (const float2*)(g_uT + (size_t)tn * (INx * Bb) + (ks * 4) * Bb + gbase + m0);
      const float*  wp = s_w1 + (Hh + ks * 4) * NC1g + cs * 8;
      #pragma unroll
      for (int p = 0; p < 8; p++) acc1u[p] = 0ull;
      #pragma unroll
      for (int k = 0; k < 4; k++) {
        float2 xv = up[k * (Bb / 2)];
        ull x0b = bcast2(xv.x), x1b = bcast2(xv.y);
        const ulonglong2* wv = (const ulonglong2*)(wp + k * NC1g);
        ulonglong2 wA = wv[0], wB = wv[1];
        asm("fma.rn.f32x2 %0, %1, %2, %0;" : "+l"(acc1u[0]) : "l"(x0b), "l"(wA.x));
        asm("fma.rn.f32x2 %0, %1, %2, %0;" : "+l"(acc1u[1]) : "l"(x0b), "l"(wA.y));
        asm("fma.rn.f32x2 %0, %1, %2, %0;" : "+l"(acc1u[2]) : "l"(x0b), "l"(wB.x));
        asm("fma.rn.f32x2 %0, %1, %2, %0;" : "+l"(acc1u[3]) : "l"(x0b), "l"(wB.y));
        asm("fma.rn.f32x2 %0, %1, %2, %0;" : "+l"(acc1u[4]) : "l"(x1b), "l"(wA.x));
        asm("fma.rn.f32x2 %0, %1, %2, %0;" : "+l"(acc1u[5]) : "l"(x1b), "l"(wA.y));
        asm("fma.rn.f32x2 %0, %1, %2, %0;" : "+l"(acc1u[6]) : "l"(x1b), "l"(wB.x));
        asm("fma.rn.f32x2 %0, %1, %2, %0;" : "+l"(acc1u[7]) : "l"(x1b), "l"(wB.y));
      }
    }
    if (tid == 0) { while (poll_at(barp) < tg) { } }
    __syncthreads();
  }
}

// Runs BEFORE gru_main each invocation: resets all barrier counters and keeps
// gru_main as ncu launch #6 (-s 5 -c 1).
__global__ void zero_bar_kernel() {
  g_bar = 0u;
  for (int g = 0; g < GRP; g++) g_barG[g * 32] = 0u;
}

extern "C" void kernel_launch(void* const* d_in, const int* in_sizes, int n_in,
                              void* d_out, int out_size) {
  // Resolve inputs by UNIQUE element counts (immune to metadata ordering).
  const float *u = 0, *x0 = 0, *kernel_fz = 0, *bias_fz = 0,
              *kernel_r = 0, *bias_r = 0, *W_out = 0, *b_out = 0;
  for (int i = 0; i < n_in; i++) {
    const float* p = (const float*)d_in[i];
    switch (in_sizes[i]) {
      case 8388608: u         = p; break;  // 64*2048*64
      case 32768:   x0        = p; break;  // 64*1*512
      case 589824:  kernel_fz = p; break;  // 576*1024
      case 1024:    bias_fz   = p; break;
      case 294912:  kernel_r  = p; break;  // 576*512
      case 512:     bias_r    = p; break;
      case 16384:   W_out     = p; break;  // 32*512
      case 32:      b_out     = p; break;
      default: break;
    }
  }
  if (!u || !x0 || !kernel_fz || !bias_fz || !kernel_r || !bias_r || !W_out || !b_out) {
    u         = (const float*)d_in[0];
    x0        = (const float*)d_in[1];
    kernel_fz = (const float*)d_in[2];
    bias_fz   = (const float*)d_in[3];
    kernel_r  = (const float*)d_in[4];
    bias_r    = (const float*)d_in[5];
    W_out     = (const float*)d_in[6];
    b_out     = (const float*)d_in[7];
  }
  float* out = (float*)d_out;

  static int smem_set = 0;
  if (!smem_set) {
    cudaFuncSetAttribute(gru_main, cudaFuncAttributeMaxDynamicSharedMemorySize,
                         SMEM_BYTES);
    smem_set = 1;
  }

  zero_bar_kernel<<<1, 1>>>();

  void* args[] = { (void*)&u, (void*)&x0,
                   (void*)&kernel_fz, (void*)&bias_fz, (void*)&kernel_r,
                   (void*)&bias_r,    (void*)&W_out,   (void*)&b_out,
                   (void*)&out };
  cudaLaunchCooperativeKernel((const void*)gru_main, dim3(NCTA), dim3(NTHR),
                              args, SMEM_BYTES, (cudaStream_t)0);
}